// round 1
// baseline (speedup 1.0000x reference)
#include <cuda_runtime.h>

// Problem constants (SplineConv: N=100000, E=1.6M, DIM=2, K=5, deg-1 open spline,
// M_in=M_out=32, K_TOT=25). Scratch sized to the fixed problem shape.
#define MAXN 100000
#define MAXE 1600000
#define KTOT 25
#define KM   800   // KTOT * 32 outputs per node in Z

// ---------------- device scratch (allocation-free per harness rules) ----------------
__device__ float g_Z[(size_t)MAXN * KM];   // 320 MB: Z[n,k,o] = sum_i x[n,i] * W[k,i,o]
__device__ float g_deg[MAXN];
__device__ int   g_is64;                   // edge_index dtype flag (1 = int64)

// ---------------- packed f32x2 helpers (Blackwell FFMA2, PTX-only) ----------------
__device__ __forceinline__ unsigned long long pack2(float v) {
    unsigned long long r;
    asm("mov.b64 %0, {%1, %1};" : "=l"(r) : "f"(v));
    return r;
}
__device__ __forceinline__ unsigned long long fma2(unsigned long long a,
                                                   unsigned long long b,
                                                   unsigned long long c) {
    unsigned long long d;
    asm("fma.rn.f32x2 %0, %1, %2, %3;" : "=l"(d) : "l"(a), "l"(b), "l"(c));
    return d;
}

// ---------------- dtype detection: int64 edge_index has zero high words ----------------
__global__ void k_detect(const unsigned int* __restrict__ w, int nwords) {
    __shared__ int nz;
    if (threadIdx.x == 0) nz = 0;
    __syncthreads();
    int lim = nwords < 4096 ? nwords : 4096;
    int any = 0;
    for (int i = 1 + 2 * (int)threadIdx.x; i < lim; i += 2 * (int)blockDim.x)
        if (w[i] != 0u) any = 1;
    if (any) atomicOr(&nz, 1);
    __syncthreads();
    if (threadIdx.x == 0) g_is64 = (nz == 0) ? 1 : 0;
}

// ---------------- zero output accumulator + degree ----------------
__global__ void k_zero(float* __restrict__ out, int nout, int ndeg) {
    int i = blockIdx.x * blockDim.x + threadIdx.x;
    if (i < nout)             out[i] = 0.0f;
    else if (i < nout + ndeg) g_deg[i - nout] = 0.0f;
}

// ---------------- Z = x @ W  (per-node, all 25 kernel slots), f32x2 packed ----------------
__global__ __launch_bounds__(256, 2)
void k_zgemm(const float* __restrict__ x, const float* __restrict__ w, int N) {
    extern __shared__ float sW[];  // 25*32*32 floats = 102400 B
    {
        const float4* src = (const float4*)w;
        float4*       dst = (float4*)sW;
        for (int i = threadIdx.x; i < KTOT * 32 * 32 / 4; i += blockDim.x)
            dst[i] = src[i];
    }
    __syncthreads();

    int n = blockIdx.x * blockDim.x + threadIdx.x;
    if (n >= N) return;

    // x row -> 32 broadcast-packed f32x2 registers
    unsigned long long xp[32];
    const float4* xv = (const float4*)(x + (size_t)n * 32);
#pragma unroll
    for (int j = 0; j < 8; j++) {
        float4 t = xv[j];
        xp[4 * j + 0] = pack2(t.x);
        xp[4 * j + 1] = pack2(t.y);
        xp[4 * j + 2] = pack2(t.z);
        xp[4 * j + 3] = pack2(t.w);
    }

    float* zp = g_Z + (size_t)n * KM;
    for (int k = 0; k < KTOT; k++) {
        unsigned long long acc[16];  // 32 outputs as 16 f32x2 pairs
#pragma unroll
        for (int j = 0; j < 16; j++) acc[j] = 0ull;

        const ulonglong2* wr = (const ulonglong2*)(sW + k * 1024);
#pragma unroll 4
        for (int i = 0; i < 32; i++) {
            unsigned long long xi = xp[i];
#pragma unroll
            for (int j2 = 0; j2 < 8; j2++) {
                ulonglong2 ww = wr[i * 8 + j2];        // LDS.128, warp-uniform broadcast
                acc[2 * j2]     = fma2(xi, ww.x, acc[2 * j2]);
                acc[2 * j2 + 1] = fma2(xi, ww.y, acc[2 * j2 + 1]);
            }
        }
        ulonglong2* zo = (ulonglong2*)(zp + k * 32);
#pragma unroll
        for (int t = 0; t < 8; t++) zo[t] = make_ulonglong2(acc[2 * t], acc[2 * t + 1]);
    }
}

// ---------------- edge phase: bilinear gather of Z rows + coalesced RED ----------------
__global__ __launch_bounds__(256)
void k_edge(const void* __restrict__ ei, const float* __restrict__ pseudo,
            float* __restrict__ out, int E) {
    int gw   = (blockIdx.x * blockDim.x + threadIdx.x) >> 5;  // one warp per edge
    int lane = threadIdx.x & 31;
    if (gw >= E) return;

    int row, col;
    if (g_is64) {
        const long long* p = (const long long*)ei;
        row = (int)p[gw];
        col = (int)p[(size_t)E + gw];
    } else {
        const int* p = (const int*)ei;
        row = p[gw];
        col = p[E + gw];
    }

    float2 ps = ((const float2*)pseudo)[gw];
    float px = ps.x * 4.0f, py = ps.y * 4.0f;   // scale = K-1 (open spline)
    float lx = floorf(px), ly = floorf(py);
    lx = fminf(fmaxf(lx, 0.0f), 3.0f);          // clamp lo to [0, K-2]; frac absorbs edge
    ly = fminf(fmaxf(ly, 0.0f), 3.0f);
    float fx = px - lx, fy = py - ly;

    int k0 = ((int)ly * 5 + (int)lx) * 32;      // flat slot = ix + 5*iy; taps k,k+1,k+5,k+6
    const float* zb = g_Z + (size_t)col * KM + k0 + lane;
    float z00 = zb[0];     // (ix  , iy  )
    float z10 = zb[32];    // (ix+1, iy  )
    float z01 = zb[160];   // (ix  , iy+1)
    float z11 = zb[192];   // (ix+1, iy+1)

    float gx0 = 1.0f - fx, gy0 = 1.0f - fy;
    float v = gy0 * (gx0 * z00 + fx * z10) + fy * (gx0 * z01 + fx * z11);

    atomicAdd(out + (size_t)row * 32 + lane, v);   // coalesced 128B RED per edge
    if (lane == 0) atomicAdd(&g_deg[row], 1.0f);
}

// ---------------- finalize: mean-divide + root term + bias ----------------
__global__ __launch_bounds__(256)
void k_final(const float* __restrict__ x, const float* __restrict__ rootw,
             const float* __restrict__ bias, float* __restrict__ out, int N) {
    __shared__ float sR[1024];
    __shared__ float sB[32];
    for (int i = threadIdx.x; i < 1024; i += blockDim.x) sR[i] = rootw[i];
    if (threadIdx.x < 32) sB[threadIdx.x] = bias[threadIdx.x];
    __syncthreads();

    int gid = blockIdx.x * blockDim.x + threadIdx.x;
    if (gid >= N * 32) return;
    int n = gid >> 5, o = gid & 31;   // warp == one node, lane == output channel

    float xv  = x[gid];               // coalesced: x[n, lane]
    float acc = 0.0f;
#pragma unroll
    for (int i = 0; i < 32; i++) {
        float xi = __shfl_sync(0xffffffffu, xv, i);
        acc += xi * sR[i * 32 + o];
    }
    float d = fmaxf(g_deg[n], 1.0f);
    out[gid] = out[gid] / d + acc + sB[o];
}

// ---------------- launch ----------------
extern "C" void kernel_launch(void* const* d_in, const int* in_sizes, int n_in,
                              void* d_out, int out_size) {
    const float* x      = (const float*)d_in[0];
    const void*  ei     = d_in[1];
    const float* pseudo = (const float*)d_in[2];
    const float* weight = (const float*)d_in[3];
    const float* rootw  = (const float*)d_in[4];
    const float* bias   = (const float*)d_in[5];
    float*       out    = (float*)d_out;

    int N = in_sizes[0] / 32;
    int E = in_sizes[2] / 2;

    k_detect<<<1, 256>>>((const unsigned int*)ei, 2 * E);

    int ztot = N * 32 + N;
    k_zero<<<(ztot + 255) / 256, 256>>>(out, N * 32, N);

    cudaFuncSetAttribute(k_zgemm, cudaFuncAttributeMaxDynamicSharedMemorySize, 102400);
    k_zgemm<<<(N + 255) / 256, 256, 102400>>>(x, weight, N);

    k_edge<<<(E + 7) / 8, 256>>>(ei, pseudo, out, E);

    k_final<<<(N * 32 + 255) / 256, 256>>>(x, rootw, bias, out, N);
}

// round 2
// speedup vs baseline: 2.1189x; 2.1189x over previous
#include <cuda_runtime.h>
#include <cuda_fp16.h>

// SplineConv: N=100000, E=1.6M, DIM=2, K=5, deg-1 open spline, M_in=M_out=32, K_TOT=25.
#define MAXN 100000
#define KTOT 25
#define KM   800   // KTOT * 32 Z-channels per node

// ---------------- device scratch (allocation-free) ----------------
__device__ __half g_Zh[(size_t)MAXN * KM];   // 160 MB fp16 Z[n,k,o]
__device__ float  g_deg[MAXN];
__device__ int    g_is64;

// ---------------- packed f32x2 helpers (Blackwell FFMA2, PTX-only) ----------------
__device__ __forceinline__ unsigned long long pack2(float v) {
    unsigned long long r;
    asm("mov.b64 %0, {%1, %1};" : "=l"(r) : "f"(v));
    return r;
}
__device__ __forceinline__ unsigned long long fma2(unsigned long long a,
                                                   unsigned long long b,
                                                   unsigned long long c) {
    unsigned long long d;
    asm("fma.rn.f32x2 %0, %1, %2, %3;" : "=l"(d) : "l"(a), "l"(b), "l"(c));
    return d;
}
// f32x2 (even=lo, odd=hi) -> packed half2 {lo=even, hi=odd}
__device__ __forceinline__ unsigned int h2pack(unsigned long long v) {
    unsigned int lo, hi, r;
    asm("mov.b64 {%0, %1}, %2;" : "=r"(lo), "=r"(hi) : "l"(v));
    float flo = __uint_as_float(lo), fhi = __uint_as_float(hi);
    asm("cvt.rn.f16x2.f32 %0, %1, %2;" : "=r"(r) : "f"(fhi), "f"(flo));
    return r;
}

// ---------------- dtype detection: int64 edge_index has zero high words ----------------
__global__ void k_detect(const unsigned int* __restrict__ w, int nwords) {
    __shared__ int nz;
    if (threadIdx.x == 0) nz = 0;
    __syncthreads();
    int lim = nwords < 4096 ? nwords : 4096;
    int any = 0;
    for (int i = 1 + 2 * (int)threadIdx.x; i < lim; i += 2 * (int)blockDim.x)
        if (w[i] != 0u) any = 1;
    if (any) atomicOr(&nz, 1);
    __syncthreads();
    if (threadIdx.x == 0) g_is64 = (nz == 0) ? 1 : 0;
}

// ---------------- zero output accumulator + degree ----------------
__global__ void k_zero(float* __restrict__ out, int nout, int ndeg) {
    int i = blockIdx.x * blockDim.x + threadIdx.x;
    if (i < nout)             out[i] = 0.0f;
    else if (i < nout + ndeg) g_deg[i - nout] = 0.0f;
}

// ---------------- Z = x @ W : 2 nodes/thread, f32x2 FMA, fp16 store ----------------
__global__ __launch_bounds__(128, 2)
void k_zgemm(const float* __restrict__ x, const float* __restrict__ w, int N) {
    extern __shared__ float sW[];  // 25*32*32 floats = 102400 B
    {
        const float4* src = (const float4*)w;
        float4*       dst = (float4*)sW;
        for (int i = threadIdx.x; i < KTOT * 1024 / 4; i += 128)
            dst[i] = src[i];
    }
    __syncthreads();

    int n0 = blockIdx.x * 256 + threadIdx.x;   // block covers 256 nodes
    int n1 = n0 + 128;

    float x0[32], x1[32];
    if (n0 < N) {
        const float4* p = (const float4*)(x + (size_t)n0 * 32);
#pragma unroll
        for (int j = 0; j < 8; j++) {
            float4 t = p[j];
            x0[4*j] = t.x; x0[4*j+1] = t.y; x0[4*j+2] = t.z; x0[4*j+3] = t.w;
        }
    } else {
#pragma unroll
        for (int j = 0; j < 32; j++) x0[j] = 0.0f;
    }
    if (n1 < N) {
        const float4* p = (const float4*)(x + (size_t)n1 * 32);
#pragma unroll
        for (int j = 0; j < 8; j++) {
            float4 t = p[j];
            x1[4*j] = t.x; x1[4*j+1] = t.y; x1[4*j+2] = t.z; x1[4*j+3] = t.w;
        }
    } else {
#pragma unroll
        for (int j = 0; j < 32; j++) x1[j] = 0.0f;
    }

    for (int k = 0; k < KTOT; k++) {
        unsigned long long a0[16], a1[16];
#pragma unroll
        for (int j = 0; j < 16; j++) { a0[j] = 0ull; a1[j] = 0ull; }

        const ulonglong2* wr = (const ulonglong2*)(sW + k * 1024);
#pragma unroll 4
        for (int i = 0; i < 32; i++) {
            unsigned long long xi0 = pack2(x0[i]);
            unsigned long long xi1 = pack2(x1[i]);
#pragma unroll
            for (int j = 0; j < 8; j++) {
                ulonglong2 ww = wr[i * 8 + j];       // one LDS.128 feeds 4 fma2
                a0[2*j]   = fma2(xi0, ww.x, a0[2*j]);
                a0[2*j+1] = fma2(xi0, ww.y, a0[2*j+1]);
                a1[2*j]   = fma2(xi1, ww.x, a1[2*j]);
                a1[2*j+1] = fma2(xi1, ww.y, a1[2*j+1]);
            }
        }

        if (n0 < N) {
            unsigned int h[16];
#pragma unroll
            for (int j = 0; j < 16; j++) h[j] = h2pack(a0[j]);
            uint4* zo = (uint4*)(g_Zh + (size_t)n0 * KM + k * 32);
            zo[0] = make_uint4(h[0],  h[1],  h[2],  h[3]);
            zo[1] = make_uint4(h[4],  h[5],  h[6],  h[7]);
            zo[2] = make_uint4(h[8],  h[9],  h[10], h[11]);
            zo[3] = make_uint4(h[12], h[13], h[14], h[15]);
        }
        if (n1 < N) {
            unsigned int h[16];
#pragma unroll
            for (int j = 0; j < 16; j++) h[j] = h2pack(a1[j]);
            uint4* zo = (uint4*)(g_Zh + (size_t)n1 * KM + k * 32);
            zo[0] = make_uint4(h[0],  h[1],  h[2],  h[3]);
            zo[1] = make_uint4(h[4],  h[5],  h[6],  h[7]);
            zo[2] = make_uint4(h[8],  h[9],  h[10], h[11]);
            zo[3] = make_uint4(h[12], h[13], h[14], h[15]);
        }
    }
}

// ---------------- edge phase: bilinear gather of fp16 Z rows + coalesced RED ----------------
__global__ __launch_bounds__(256)
void k_edge(const void* __restrict__ ei, const float* __restrict__ pseudo,
            float* __restrict__ out, int E) {
    int lane   = threadIdx.x & 31;
    int warp   = (blockIdx.x * blockDim.x + threadIdx.x) >> 5;
    int nwarps = (gridDim.x * blockDim.x) >> 5;
    int is64   = g_is64;

    const long long* p64 = (const long long*)ei;
    const int*       p32 = (const int*)ei;

    for (int e = warp; e < E; e += nwarps) {
        int row, col;
        if (is64) { row = (int)p64[e]; col = (int)p64[(size_t)E + e]; }
        else      { row = p32[e];      col = p32[E + e]; }

        float2 ps = ((const float2*)pseudo)[e];
        float px = ps.x * 4.0f, py = ps.y * 4.0f;   // scale = K-1 (open spline)
        float lx = fminf(fmaxf(floorf(px), 0.0f), 3.0f);
        float ly = fminf(fmaxf(floorf(py), 0.0f), 3.0f);
        float fx = px - lx, fy = py - ly;

        int k0 = ((int)ly * 5 + (int)lx) * 32;      // taps k, k+1, k+5, k+6
        const __half* zb = g_Zh + (size_t)col * KM + k0 + lane;
        float z00 = __half2float(zb[0]);
        float z10 = __half2float(zb[32]);
        float z01 = __half2float(zb[160]);
        float z11 = __half2float(zb[192]);

        float gx0 = 1.0f - fx, gy0 = 1.0f - fy;
        float v = gy0 * (gx0 * z00 + fx * z10) + fy * (gx0 * z01 + fx * z11);

        atomicAdd(out + (size_t)row * 32 + lane, v);
        if (lane == 0) atomicAdd(&g_deg[row], 1.0f);
    }
}

// ---------------- finalize: mean-divide + root term + bias ----------------
__global__ __launch_bounds__(256)
void k_final(const float* __restrict__ x, const float* __restrict__ rootw,
             const float* __restrict__ bias, float* __restrict__ out, int N) {
    __shared__ float sR[1024];
    __shared__ float sB[32];
    for (int i = threadIdx.x; i < 1024; i += blockDim.x) sR[i] = rootw[i];
    if (threadIdx.x < 32) sB[threadIdx.x] = bias[threadIdx.x];
    __syncthreads();

    int gid = blockIdx.x * blockDim.x + threadIdx.x;
    if (gid >= N * 32) return;
    int n = gid >> 5, o = gid & 31;

    float xv  = x[gid];
    float acc = 0.0f;
#pragma unroll
    for (int i = 0; i < 32; i++) {
        float xi = __shfl_sync(0xffffffffu, xv, i);
        acc += xi * sR[i * 32 + o];
    }
    float d = fmaxf(g_deg[n], 1.0f);
    out[gid] = out[gid] / d + acc + sB[o];
}

// ---------------- launch ----------------
extern "C" void kernel_launch(void* const* d_in, const int* in_sizes, int n_in,
                              void* d_out, int out_size) {
    const float* x      = (const float*)d_in[0];
    const void*  ei     = d_in[1];
    const float* pseudo = (const float*)d_in[2];
    const float* weight = (const float*)d_in[3];
    const float* rootw  = (const float*)d_in[4];
    const float* bias   = (const float*)d_in[5];
    float*       out    = (float*)d_out;

    int N = in_sizes[0] / 32;
    int E = in_sizes[2] / 2;

    k_detect<<<1, 256>>>((const unsigned int*)ei, 2 * E);

    int ztot = N * 32 + N;
    k_zero<<<(ztot + 255) / 256, 256>>>(out, N * 32, N);

    cudaFuncSetAttribute(k_zgemm, cudaFuncAttributeMaxDynamicSharedMemorySize, 102400);
    k_zgemm<<<(N + 255) / 256, 128, 102400>>>(x, weight, N);

    k_edge<<<2048, 256>>>(ei, pseudo, out, E);

    k_final<<<(N * 32 + 255) / 256, 256>>>(x, rootw, bias, out, N);
}

// round 4
// speedup vs baseline: 3.7062x; 1.7492x over previous
#include <cuda_runtime.h>
#include <cuda_fp16.h>
#include <stdint.h>

// SplineConv: N=100000, E=1.6M, DIM=2, K=5, deg-1 open spline, M_in=M_out=32, K_TOT=25.
#define MAXN 100000
#define KTOT 25
#define KM   800   // KTOT*32 Z-channels per node

// ---------------- device scratch (allocation-free) ----------------
__device__ __half g_Zh[(size_t)MAXN * KM];   // 160 MB fp16 Z[n, p]  (p = k*32+o)
__device__ __half g_Wh[KTOT * 32 * 32];      // [p=800][i=32] f16  (B operand, k-contiguous)
__device__ float  g_deg[MAXN];
__device__ int    g_is64;

__device__ __forceinline__ uint32_t smem_u32(const void* p) {
    uint32_t a;
    asm("{ .reg .u64 t; cvta.to.shared.u64 t, %1; cvt.u32.u64 %0, t; }" : "=r"(a) : "l"(p));
    return a;
}
__device__ __forceinline__ void ldsm_x4(uint32_t addr, uint32_t* r) {
    asm volatile("ldmatrix.sync.aligned.m8n8.x4.shared.b16 {%0,%1,%2,%3}, [%4];"
        : "=r"(r[0]), "=r"(r[1]), "=r"(r[2]), "=r"(r[3]) : "r"(addr));
}
__device__ __forceinline__ void mma16816(float* d, const uint32_t* a, uint32_t b0, uint32_t b1) {
    asm volatile("mma.sync.aligned.m16n8k16.row.col.f32.f16.f16.f32 "
        "{%0,%1,%2,%3}, {%4,%5,%6,%7}, {%8,%9}, {%0,%1,%2,%3};"
        : "+f"(d[0]), "+f"(d[1]), "+f"(d[2]), "+f"(d[3])
        : "r"(a[0]), "r"(a[1]), "r"(a[2]), "r"(a[3]), "r"(b0), "r"(b1));
}
__device__ __forceinline__ uint32_t packh2(float lo, float hi) {
    uint32_t r;
    asm("cvt.rn.f16x2.f32 %0, %1, %2;" : "=r"(r) : "f"(hi), "f"(lo));
    return r;
}

// ---------------- dtype detection: int64 edge_index has zero high words ----------------
__global__ void k_detect(const unsigned int* __restrict__ w, int nwords) {
    __shared__ int nz;
    if (threadIdx.x == 0) nz = 0;
    __syncthreads();
    int lim = nwords < 4096 ? nwords : 4096;
    int any = 0;
    for (int i = 1 + 2 * (int)threadIdx.x; i < lim; i += 2 * (int)blockDim.x)
        if (w[i] != 0u) any = 1;
    if (any) atomicOr(&nz, 1);
    __syncthreads();
    if (threadIdx.x == 0) g_is64 = (nz == 0) ? 1 : 0;
}

// ---------------- W transpose+convert: g_Wh[p][i] = W[k,i,o], p=k*32+o ----------------
__global__ void k_prep(const float* __restrict__ w) {
    int t = blockIdx.x * blockDim.x + threadIdx.x;
    if (t >= KTOT * 1024) return;
    int p = t >> 5, i = t & 31;
    int k = p >> 5, o = p & 31;
    g_Wh[t] = __float2half(w[k * 1024 + i * 32 + o]);
}

// ---------------- zero output accumulator + degree ----------------
__global__ void k_zero(float* __restrict__ out, int nout, int ndeg) {
    int i = blockIdx.x * blockDim.x + threadIdx.x;
    if (i < nout)             out[i] = 0.0f;
    else if (i < nout + ndeg) g_deg[i - nout] = 0.0f;
}

// ---------------- Z = x @ Wt via mma.sync m16n8k16 (legacy HMMA path) ----------------
// Block: 256 thr (8 warps), 128 nodes. A[128x32]f16 smem (80B rows, conflict-free
// ldmatrix), B=Wt[800x32]f16 smem (80B rows). Warp w: rows w*16..w*16+15, all 800 cols.
#define SA_BYTES 10240           // 128 * 80
#define SB_OFF   10240
#define ZG_SMEM  (10240 + 64000) // + 800 * 80

__global__ __launch_bounds__(256, 2)
void k_zgemm_mma(const float* __restrict__ x, int N) {
    extern __shared__ __align__(128) char smem[];
    char* sA = smem;
    char* sB = smem + SB_OFF;
    int tid = threadIdx.x;
    int n0 = blockIdx.x * 128;

    // stage B: 800 rows x 64B, padded to 80B
    for (int g = tid; g < 3200; g += 256) {
        int row = g >> 2, sub = g & 3;
        *(uint4*)(sB + row * 80 + sub * 16) = *(const uint4*)(g_Wh + row * 32 + sub * 8);
    }
    // stage A: 128 node rows x 32 f32 -> f16 (64B used of 80B row)
    for (int g = tid; g < 512; g += 256) {
        int row = g >> 2, sub = g & 3;
        int n = n0 + row;
        uint4 hv = make_uint4(0, 0, 0, 0);
        if (n < N) {
            const float4* xp = (const float4*)(x + (size_t)n * 32 + sub * 8);
            float4 a = xp[0], b = xp[1];
            hv.x = packh2(a.x, a.y);
            hv.y = packh2(a.z, a.w);
            hv.z = packh2(b.x, b.y);
            hv.w = packh2(b.z, b.w);
        }
        *(uint4*)(sA + row * 80 + sub * 16) = hv;
    }
    __syncthreads();

    int wid = tid >> 5, lane = tid & 31;
    int m0 = wid * 16;
    int r = lane & 7, sel = lane >> 3;

    // A fragments: m16k16 x2 (k=0..15, 16..31)
    uint32_t aaddr = smem_u32(sA + (m0 + r + ((sel & 1) ? 8 : 0)) * 80 + (sel >> 1) * 16);
    uint32_t a[8];
    ldsm_x4(aaddr,      a);      // k-step 0
    ldsm_x4(aaddr + 32, a + 4);  // k-step 1

    // B ldmatrix per-lane offset: matrices (n0-7,k0),(n0-7,k8),(n8-15,k0),(n8-15,k8)
    uint32_t sBu  = smem_u32(sB);
    uint32_t bofs = (r + ((sel >> 1) ? 8 : 0)) * 80 + (sel & 1) * 16;

    int mrow  = lane >> 2;         // 0..7
    int ncol0 = (lane & 3) * 2;
    int node_lo = n0 + m0 + mrow;
    int node_hi = node_lo + 8;
    __half* z_lo = g_Zh + (size_t)node_lo * KM;
    __half* z_hi = g_Zh + (size_t)node_hi * KM;
    bool ok_lo = node_lo < N, ok_hi = node_hi < N;

    for (int nb = 0; nb < KM; nb += 16) {
        uint32_t baddr = sBu + nb * 80 + bofs;
        uint32_t b[8];
        ldsm_x4(baddr,      b);      // k-step 0: b0=(n0,k0-7) b1=(n0,k8-15) b2=(n8,..) b3
        ldsm_x4(baddr + 32, b + 4);  // k-step 1

        float acc0[4] = {0.f, 0.f, 0.f, 0.f};
        float acc1[4] = {0.f, 0.f, 0.f, 0.f};
        mma16816(acc0, a,     b[0], b[1]);
        mma16816(acc0, a + 4, b[4], b[5]);
        mma16816(acc1, a,     b[2], b[3]);
        mma16816(acc1, a + 4, b[6], b[7]);

        if (ok_lo) {
            *(uint32_t*)(z_lo + nb + ncol0)     = packh2(acc0[0], acc0[1]);
            *(uint32_t*)(z_lo + nb + 8 + ncol0) = packh2(acc1[0], acc1[1]);
        }
        if (ok_hi) {
            *(uint32_t*)(z_hi + nb + ncol0)     = packh2(acc0[2], acc0[3]);
            *(uint32_t*)(z_hi + nb + 8 + ncol0) = packh2(acc1[2], acc1[3]);
        }
    }
}

// ---------------- edge phase: 4 edges/warp-iteration, bilinear gather + RED ----------------
__global__ __launch_bounds__(256)
void k_edge(const void* __restrict__ ei, const float* __restrict__ pseudo,
            float* __restrict__ out, int E) {
    int lane   = threadIdx.x & 31;
    int warp   = (blockIdx.x * blockDim.x + threadIdx.x) >> 5;
    int nwarps = (gridDim.x * blockDim.x) >> 5;
    int is64   = g_is64;
    const long long* p64 = (const long long*)ei;
    const int*       p32 = (const int*)ei;

    for (int q = warp * 4; q < E; q += nwarps * 4) {
        int rr[4], cc[4], kk[4];
        float wfx[4], wfy[4];
#pragma unroll
        for (int j = 0; j < 4; j++) {
            int e = q + j; if (e > E - 1) e = E - 1;
            int rI, cI;
            if (is64) { rI = (int)p64[e]; cI = (int)p64[(size_t)E + e]; }
            else      { rI = p32[e];      cI = p32[E + e]; }
            float2 ps = ((const float2*)pseudo)[e];
            float px = ps.x * 4.0f, py = ps.y * 4.0f;
            float lx = fminf(fmaxf(floorf(px), 0.0f), 3.0f);
            float ly = fminf(fmaxf(floorf(py), 0.0f), 3.0f);
            rr[j] = rI; cc[j] = cI;
            kk[j] = ((int)ly * 5 + (int)lx) * 32;
            wfx[j] = px - lx; wfy[j] = py - ly;
        }
        float z[4][4];
#pragma unroll
        for (int j = 0; j < 4; j++) {
            const __half* zb = g_Zh + (size_t)cc[j] * KM + kk[j] + lane;
            z[j][0] = __half2float(zb[0]);
            z[j][1] = __half2float(zb[32]);
            z[j][2] = __half2float(zb[160]);
            z[j][3] = __half2float(zb[192]);
        }
#pragma unroll
        for (int j = 0; j < 4; j++) {
            if (q + j < E) {
                float fx = wfx[j], fy = wfy[j];
                float v = (1.0f - fy) * ((1.0f - fx) * z[j][0] + fx * z[j][1])
                        +         fy  * ((1.0f - fx) * z[j][2] + fx * z[j][3]);
                atomicAdd(out + (size_t)rr[j] * 32 + lane, v);
                if (lane == j) atomicAdd(&g_deg[rr[j]], 1.0f);
            }
        }
    }
}

// ---------------- finalize: mean-divide + root term + bias ----------------
__global__ __launch_bounds__(256)
void k_final(const float* __restrict__ x, const float* __restrict__ rootw,
             const float* __restrict__ bias, float* __restrict__ out, int N) {
    __shared__ float sR[1024];
    __shared__ float sB[32];
    for (int i = threadIdx.x; i < 1024; i += blockDim.x) sR[i] = rootw[i];
    if (threadIdx.x < 32) sB[threadIdx.x] = bias[threadIdx.x];
    __syncthreads();

    int gid = blockIdx.x * blockDim.x + threadIdx.x;
    if (gid >= N * 32) return;
    int n = gid >> 5, o = gid & 31;

    float xv  = x[gid];
    float acc = 0.0f;
#pragma unroll
    for (int i = 0; i < 32; i++) {
        float xi = __shfl_sync(0xffffffffu, xv, i);
        acc += xi * sR[i * 32 + o];
    }
    float d = fmaxf(g_deg[n], 1.0f);
    out[gid] = out[gid] / d + acc + sB[o];
}

// ---------------- launch ----------------
extern "C" void kernel_launch(void* const* d_in, const int* in_sizes, int n_in,
                              void* d_out, int out_size) {
    const float* x      = (const float*)d_in[0];
    const void*  ei     = d_in[1];
    const float* pseudo = (const float*)d_in[2];
    const float* weight = (const float*)d_in[3];
    const float* rootw  = (const float*)d_in[4];
    const float* bias   = (const float*)d_in[5];
    float*       out    = (float*)d_out;

    int N = in_sizes[0] / 32;
    int E = in_sizes[2] / 2;

    k_detect<<<1, 256>>>((const unsigned int*)ei, 2 * E);
    k_prep<<<(KTOT * 1024 + 255) / 256, 256>>>(weight);

    int ztot = N * 32 + N;
    k_zero<<<(ztot + 255) / 256, 256>>>(out, N * 32, N);

    cudaFuncSetAttribute(k_zgemm_mma, cudaFuncAttributeMaxDynamicSharedMemorySize, ZG_SMEM);
    k_zgemm_mma<<<(N + 127) / 128, 256, ZG_SMEM>>>(x, N);

    k_edge<<<2048, 256>>>(ei, pseudo, out, E);

    k_final<<<(N * 32 + 255) / 256, 256>>>(x, rootw, bias, out, N);
}

// round 5
// speedup vs baseline: 3.9528x; 1.0665x over previous
#include <cuda_runtime.h>
#include <cuda_fp16.h>
#include <stdint.h>

// SplineConv: N=100000, E=1.6M, DIM=2, K=5, deg-1 open spline, M_in=M_out=32, K_TOT=25.
#define MAXN 100000
#define MAXE 1600000
#define KTOT 25
#define KM   800   // KTOT*32 Z-channels per node

// ---------------- device scratch (allocation-free) ----------------
__device__ __half g_Zh[(size_t)MAXN * KM];   // 160 MB fp16 Z[n, p]  (p = k*32+o)
__device__ __half g_Wh[KTOT * 32 * 32];      // [p=800][i=32] f16  (B operand, k-contiguous)
__device__ uint4  g_edesc[MAXE];             // packed edges: {row, col|kidx<<20, fx, fy}
__device__ float  g_deg[MAXN];
__device__ int    g_is64;

__device__ __forceinline__ uint32_t smem_u32(const void* p) {
    uint32_t a;
    asm("{ .reg .u64 t; cvta.to.shared.u64 t, %1; cvt.u32.u64 %0, t; }" : "=r"(a) : "l"(p));
    return a;
}
__device__ __forceinline__ void ldsm_x4(uint32_t addr, uint32_t* r) {
    asm volatile("ldmatrix.sync.aligned.m8n8.x4.shared.b16 {%0,%1,%2,%3}, [%4];"
        : "=r"(r[0]), "=r"(r[1]), "=r"(r[2]), "=r"(r[3]) : "r"(addr));
}
__device__ __forceinline__ void mma16816(float* d, const uint32_t* a, uint32_t b0, uint32_t b1) {
    asm volatile("mma.sync.aligned.m16n8k16.row.col.f32.f16.f16.f32 "
        "{%0,%1,%2,%3}, {%4,%5,%6,%7}, {%8,%9}, {%0,%1,%2,%3};"
        : "+f"(d[0]), "+f"(d[1]), "+f"(d[2]), "+f"(d[3])
        : "r"(a[0]), "r"(a[1]), "r"(a[2]), "r"(a[3]), "r"(b0), "r"(b1));
}
__device__ __forceinline__ uint32_t packh2(float lo, float hi) {
    uint32_t r;
    asm("cvt.rn.f16x2.f32 %0, %1, %2;" : "=r"(r) : "f"(hi), "f"(lo));
    return r;
}

// ---------------- dtype detection: int64 edge_index has zero high words ----------------
__global__ void k_detect(const unsigned int* __restrict__ w, int nwords) {
    __shared__ int nz;
    if (threadIdx.x == 0) nz = 0;
    __syncthreads();
    int lim = nwords < 4096 ? nwords : 4096;
    int any = 0;
    for (int i = 1 + 2 * (int)threadIdx.x; i < lim; i += 2 * (int)blockDim.x)
        if (w[i] != 0u) any = 1;
    if (any) atomicOr(&nz, 1);
    __syncthreads();
    if (threadIdx.x == 0) g_is64 = (nz == 0) ? 1 : 0;
}

// ---------------- zero output accumulator + degree ----------------
__global__ void k_zero(float* __restrict__ out, int nout, int ndeg) {
    int i = blockIdx.x * blockDim.x + threadIdx.x;
    if (i < nout)             out[i] = 0.0f;
    else if (i < nout + ndeg) g_deg[i - nout] = 0.0f;
}

// ---------------- edge preprocessing: pack descriptor + degree count ----------------
__global__ __launch_bounds__(256)
void k_eprep(const void* __restrict__ ei, const float* __restrict__ pseudo, int E) {
    int e = blockIdx.x * blockDim.x + threadIdx.x;
    if (e >= E) return;
    int r, c;
    if (g_is64) {
        const long long* p = (const long long*)ei;
        r = (int)p[e]; c = (int)p[(size_t)E + e];
    } else {
        const int* p = (const int*)ei;
        r = p[e]; c = p[E + e];
    }
    float2 ps = ((const float2*)pseudo)[e];
    float px = ps.x * 4.0f, py = ps.y * 4.0f;   // scale = K-1 (open spline)
    float lx = fminf(fmaxf(floorf(px), 0.0f), 3.0f);
    float ly = fminf(fmaxf(floorf(py), 0.0f), 3.0f);
    int kidx = (int)ly * 5 + (int)lx;           // 0..18
    g_edesc[e] = make_uint4((uint32_t)r,
                            (uint32_t)c | ((uint32_t)kidx << 20),
                            __float_as_uint(px - lx),
                            __float_as_uint(py - ly));
    atomicAdd(&g_deg[r], 1.0f);
}

// ---------------- W transpose+convert: g_Wh[p][i] = W[k,i,o], p=k*32+o ----------------
__global__ void k_prep(const float* __restrict__ w) {
    int t = blockIdx.x * blockDim.x + threadIdx.x;
    if (t >= KTOT * 1024) return;
    int p = t >> 5, i = t & 31;
    int k = p >> 5, o = p & 31;
    g_Wh[t] = __float2half(w[k * 1024 + i * 32 + o]);
}

// ---------------- Z = x @ Wt via mma.sync m16n8k16, split-N over gridDim.y ----------------
// Block: 256 thr (8 warps), 128 nodes x 400 cols. A[128x32]f16 + B[400x32]f16 in smem
// (80B-padded rows, conflict-free ldmatrix). Warp w: rows w*16..+15, 400 cols.
#define NB_COLS 400
#define SB_OFF  10240                    // A: 128*80
#define ZG_SMEM (10240 + NB_COLS * 80)   // + B: 400*80 = 42240

__global__ __launch_bounds__(256, 4)
void k_zgemm_mma(const float* __restrict__ x, int N) {
    extern __shared__ __align__(128) char smem[];
    char* sA = smem;
    char* sB = smem + SB_OFF;
    int tid = threadIdx.x;
    int n0 = blockIdx.x * 128;
    int colbase = blockIdx.y * NB_COLS;

    // stage B: NB_COLS rows x 64B, padded to 80B
    for (int g = tid; g < NB_COLS * 4; g += 256) {
        int row = g >> 2, sub = g & 3;
        *(uint4*)(sB + row * 80 + sub * 16) =
            *(const uint4*)(g_Wh + (colbase + row) * 32 + sub * 8);
    }
    // stage A: 128 node rows x 32 f32 -> f16
    for (int g = tid; g < 512; g += 256) {
        int row = g >> 2, sub = g & 3;
        int n = n0 + row;
        uint4 hv = make_uint4(0, 0, 0, 0);
        if (n < N) {
            const float4* xp = (const float4*)(x + (size_t)n * 32 + sub * 8);
            float4 a = xp[0], b = xp[1];
            hv.x = packh2(a.x, a.y);
            hv.y = packh2(a.z, a.w);
            hv.z = packh2(b.x, b.y);
            hv.w = packh2(b.z, b.w);
        }
        *(uint4*)(sA + row * 80 + sub * 16) = hv;
    }
    __syncthreads();

    int wid = tid >> 5, lane = tid & 31;
    int m0 = wid * 16;
    int r = lane & 7, sel = lane >> 3;

    uint32_t aaddr = smem_u32(sA + (m0 + r + ((sel & 1) ? 8 : 0)) * 80 + (sel >> 1) * 16);
    uint32_t a[8];
    ldsm_x4(aaddr,      a);
    ldsm_x4(aaddr + 32, a + 4);

    uint32_t sBu  = smem_u32(sB);
    uint32_t bofs = (r + ((sel >> 1) ? 8 : 0)) * 80 + (sel & 1) * 16;

    int mrow  = lane >> 2;
    int ncol0 = (lane & 3) * 2;
    int node_lo = n0 + m0 + mrow;
    int node_hi = node_lo + 8;
    __half* z_lo = g_Zh + (size_t)node_lo * KM + colbase;
    __half* z_hi = g_Zh + (size_t)node_hi * KM + colbase;
    bool ok_lo = node_lo < N, ok_hi = node_hi < N;

    for (int nb = 0; nb < NB_COLS; nb += 16) {
        uint32_t baddr = sBu + nb * 80 + bofs;
        uint32_t b[8];
        ldsm_x4(baddr,      b);
        ldsm_x4(baddr + 32, b + 4);

        float acc0[4] = {0.f, 0.f, 0.f, 0.f};
        float acc1[4] = {0.f, 0.f, 0.f, 0.f};
        mma16816(acc0, a,     b[0], b[1]);
        mma16816(acc0, a + 4, b[4], b[5]);
        mma16816(acc1, a,     b[2], b[3]);
        mma16816(acc1, a + 4, b[6], b[7]);

        if (ok_lo) {
            *(uint32_t*)(z_lo + nb + ncol0)     = packh2(acc0[0], acc0[1]);
            *(uint32_t*)(z_lo + nb + 8 + ncol0) = packh2(acc1[0], acc1[1]);
        }
        if (ok_hi) {
            *(uint32_t*)(z_hi + nb + ncol0)     = packh2(acc0[2], acc0[3]);
            *(uint32_t*)(z_hi + nb + 8 + ncol0) = packh2(acc1[2], acc1[3]);
        }
    }
}

// ---------------- edge phase: 6 edges/warp-iteration from packed descriptors ----------------
#define EB 6
__global__ __launch_bounds__(256, 3)
void k_edge(float* __restrict__ out, int E) {
    int lane   = threadIdx.x & 31;
    int warp   = (blockIdx.x * blockDim.x + threadIdx.x) >> 5;
    int nwarps = (gridDim.x * blockDim.x) >> 5;

    for (int q = warp * EB; q < E; q += nwarps * EB) {
        uint4 d[EB];
#pragma unroll
        for (int j = 0; j < EB; j++) {
            int e = q + j; if (e > E - 1) e = E - 1;
            d[j] = g_edesc[e];                       // 16B broadcast load
        }
        float z[EB][4];
#pragma unroll
        for (int j = 0; j < EB; j++) {
            uint32_t cp = d[j].y;
            const __half* zb = g_Zh + (size_t)(cp & 0xFFFFFu) * KM
                             + ((cp >> 20) << 5) + lane;
            z[j][0] = __half2float(zb[0]);     // tap (ix  , iy  )
            z[j][1] = __half2float(zb[32]);    // tap (ix+1, iy  )
            z[j][2] = __half2float(zb[160]);   // tap (ix  , iy+1)
            z[j][3] = __half2float(zb[192]);   // tap (ix+1, iy+1)
        }
#pragma unroll
        for (int j = 0; j < EB; j++) {
            if (q + j < E) {
                float fx = __uint_as_float(d[j].z);
                float fy = __uint_as_float(d[j].w);
                float v = (1.0f - fy) * ((1.0f - fx) * z[j][0] + fx * z[j][1])
                        +         fy  * ((1.0f - fx) * z[j][2] + fx * z[j][3]);
                atomicAdd(out + (size_t)d[j].x * 32 + lane, v);
            }
        }
    }
}

// ---------------- finalize: mean-divide + root term + bias ----------------
__global__ __launch_bounds__(256)
void k_final(const float* __restrict__ x, const float* __restrict__ rootw,
             const float* __restrict__ bias, float* __restrict__ out, int N) {
    __shared__ float sR[1024];
    __shared__ float sB[32];
    for (int i = threadIdx.x; i < 1024; i += blockDim.x) sR[i] = rootw[i];
    if (threadIdx.x < 32) sB[threadIdx.x] = bias[threadIdx.x];
    __syncthreads();

    int gid = blockIdx.x * blockDim.x + threadIdx.x;
    if (gid >= N * 32) return;
    int n = gid >> 5, o = gid & 31;

    float xv  = x[gid];
    float acc = 0.0f;
#pragma unroll
    for (int i = 0; i < 32; i++) {
        float xi = __shfl_sync(0xffffffffu, xv, i);
        acc += xi * sR[i * 32 + o];
    }
    float dgg = fmaxf(g_deg[n], 1.0f);
    out[gid] = out[gid] / dgg + acc + sB[o];
}

// ---------------- launch ----------------
extern "C" void kernel_launch(void* const* d_in, const int* in_sizes, int n_in,
                              void* d_out, int out_size) {
    const float* x      = (const float*)d_in[0];
    const void*  ei     = d_in[1];
    const float* pseudo = (const float*)d_in[2];
    const float* weight = (const float*)d_in[3];
    const float* rootw  = (const float*)d_in[4];
    const float* bias   = (const float*)d_in[5];
    float*       out    = (float*)d_out;

    int N = in_sizes[0] / 32;
    int E = in_sizes[2] / 2;

    k_detect<<<1, 256>>>((const unsigned int*)ei, 2 * E);

    int ztot = N * 32 + N;
    k_zero<<<(ztot + 255) / 256, 256>>>(out, N * 32, N);

    k_eprep<<<(E + 255) / 256, 256>>>(ei, pseudo, E);
    k_prep<<<(KTOT * 1024 + 255) / 256, 256>>>(weight);

    cudaFuncSetAttribute(k_zgemm_mma, cudaFuncAttributeMaxDynamicSharedMemorySize, ZG_SMEM);
    dim3 zg((N + 127) / 128, 2);
    k_zgemm_mma<<<zg, 256, ZG_SMEM>>>(x, N);

    k_edge<<<2048, 256>>>(out, E);

    k_final<<<(N * 32 + 255) / 256, 256>>>(x, rootw, bias, out, N);
}